// round 1
// baseline (speedup 1.0000x reference)
#include <cuda_runtime.h>

// ---------------- problem constants ----------------
#define B_    8
#define H_    56
#define W_    56
#define C_    192
#define NWH   14            // windows per side (56/4)
#define BW    1568          // total windows
#define MPAD  1600          // padded window-row count (25 * 64)
#define IND   3072          // 4*4*192
#define HID   256
#define NCL   256
#define KSPLIT 3            // GEMM1 K split (3072/3 = 1024)

// ---------------- scratch (__device__ globals; zero-init; no allocs) ------
__device__ float g_win[MPAD * IND];              // 19.7 MB
__device__ float g_tm_part[KSPLIT * MPAD * HID]; // GEMM1 split partials
__device__ float g_tm[MPAD * HID];
__device__ float g_cl[MPAD * NCL];
__device__ float g_logits[MPAD * C_];
__device__ float g_feat[MPAD * IND];             // 19.7 MB
__device__ float g_incT[2 * HID * NCL];          // inc mask transposed [512][256]

__device__ __forceinline__ float sigmoidf_(float x) {
    return 1.0f / (1.0f + __expf(-x));
}

// ---------------- K1: LayerNorm + roll(-2,-2) + window partition ----------
// one warp per pixel; lane covers channels lane+32k, k<6
__global__ void ln_partition_kernel(const float* __restrict__ x,
                                    const float* __restrict__ gamma,
                                    const float* __restrict__ beta) {
    int gwarp = (blockIdx.x * blockDim.x + threadIdx.x) >> 5;
    int lane  = threadIdx.x & 31;
    if (gwarp >= B_ * H_ * W_) return;
    const float* xr = x + (size_t)gwarp * C_;
    float v[6];
    float s = 0.f, ss = 0.f;
#pragma unroll
    for (int k = 0; k < 6; k++) {
        v[k] = xr[lane + 32 * k];
        s += v[k];
        ss += v[k] * v[k];
    }
#pragma unroll
    for (int o = 16; o > 0; o >>= 1) {
        s  += __shfl_xor_sync(0xffffffffu, s, o);
        ss += __shfl_xor_sync(0xffffffffu, ss, o);
    }
    float mean = s * (1.0f / C_);
    float var  = ss * (1.0f / C_) - mean * mean;
    float inv  = rsqrtf(var + 1e-5f);

    int p = gwarp;
    int w = p % W_;
    int h = (p / W_) % H_;
    int b = p / (H_ * W_);
    // after roll(-2,-2), this pixel lands at (hr, wr)
    int hr = (h + H_ - 2) % H_;
    int wr = (w + W_ - 2) % W_;
    int row  = b * (NWH * NWH) + (hr >> 2) * NWH + (wr >> 2);
    int base = row * IND + ((hr & 3) * 4 + (wr & 3)) * C_;
#pragma unroll
    for (int k = 0; k < 6; k++) {
        int c = lane + 32 * k;
        g_win[base + c] = (v[k] - mean) * inv * gamma[c] + beta[c];
    }
}

// ---------------- K2: pack include mask transposed --------------------
// inc = (sigmoid(inc_w) > 0.5)  <=>  inc_w > 0
__global__ void pack_inc_kernel(const float* __restrict__ inc_w) {
    int t = blockIdx.x * blockDim.x + threadIdx.x;
    if (t >= 2 * HID * NCL) return;
    int k = t / NCL, n = t % NCL;
    g_incT[t] = (inc_w[n * (2 * HID) + k] > 0.0f) ? 1.0f : 0.0f;
}

// ---------------- generic fp32 tiled GEMM ------------------------------
// C[m,n] = epi( sum_k A[m,k]*B[k,n] )
// EPI: 0 = sigmoid(acc + bias[n]);  1 = acc*scale;  2 = raw store (split-K partial)
template <int BM, int BN, int BK, int EPI>
__global__ void __launch_bounds__((BM / 4) * (BN / 4))
gemm_kernel(const float* __restrict__ A, const float* __restrict__ Bm,
            const float* __restrict__ bias, float* __restrict__ C,
            int N, int Ktot, int kPerZ, int zStride, float scale) {
    constexpr int THREADS = (BM / 4) * (BN / 4);
    __shared__ float As[BK][BM + 4];
    __shared__ float Bs[BK][BN + 4];
    int tid = threadIdx.x;
    int tx  = tid % (BN / 4);
    int ty  = tid / (BN / 4);
    int bm  = blockIdx.y * BM;
    int bn  = blockIdx.x * BN;
    int k0  = blockIdx.z * kPerZ;
    int k1  = k0 + kPerZ;
    C += (size_t)blockIdx.z * zStride;

    float acc[4][4] = {};
    for (int kb = k0; kb < k1; kb += BK) {
#pragma unroll
        for (int r = 0; r < (BM * BK) / THREADS; r++) {
            int i = tid + r * THREADS;
            int m = i / BK, k = i % BK;
            As[k][m] = A[(size_t)(bm + m) * Ktot + kb + k];
        }
#pragma unroll
        for (int r = 0; r < (BK * BN) / THREADS; r++) {
            int i = tid + r * THREADS;
            int k = i / BN, n = i % BN;
            Bs[k][n] = Bm[(size_t)(kb + k) * N + bn + n];
        }
        __syncthreads();
#pragma unroll
        for (int kk = 0; kk < BK; kk++) {
            float4 a4 = *(const float4*)&As[kk][ty * 4];
            float4 b4 = *(const float4*)&Bs[kk][tx * 4];
            float av[4] = {a4.x, a4.y, a4.z, a4.w};
            float bv[4] = {b4.x, b4.y, b4.z, b4.w};
#pragma unroll
            for (int i = 0; i < 4; i++)
#pragma unroll
                for (int j = 0; j < 4; j++)
                    acc[i][j] = fmaf(av[i], bv[j], acc[i][j]);
        }
        __syncthreads();
    }
#pragma unroll
    for (int i = 0; i < 4; i++) {
        int m = bm + ty * 4 + i;
#pragma unroll
        for (int j = 0; j < 4; j++) {
            int n   = bn + tx * 4 + j;
            float v = acc[i][j];
            if (EPI == 0)      v = sigmoidf_(v + bias[n]);
            else if (EPI == 1) v = v * scale;
            C[(size_t)m * N + n] = v;
        }
    }
}

// ---------------- combine split-K partials + bias + sigmoid -------------
__global__ void combine_tm_kernel(const float* __restrict__ b1) {
    int t = blockIdx.x * blockDim.x + threadIdx.x;
    if (t >= MPAD * HID) return;
    float v = g_tm_part[t] + g_tm_part[t + MPAD * HID] + g_tm_part[t + 2 * MPAD * HID];
    g_tm[t] = sigmoidf_(v + b1[t % HID]);
}

// ---------------- clause "min-GEMM" ------------------------------------
// clause_soft[w,cl] = min_j (1 - inc[cl,j]*(1 - lit[w,j])), lit = [tm, 1-tm]
// store As = lit-1 so inner is: val = fma(inc, lit-1, 1); acc = min(acc, val)
__global__ void __launch_bounds__(256)
clause_kernel() {
    __shared__ float As[16][68];
    __shared__ float Bs[16][68];
    int tid = threadIdx.x;
    int tx  = tid % 16;
    int ty  = tid / 16;
    int bm  = blockIdx.y * 64;
    int bn  = blockIdx.x * 64;

    float acc[4][4];
#pragma unroll
    for (int i = 0; i < 4; i++)
#pragma unroll
        for (int j = 0; j < 4; j++) acc[i][j] = 1.0f;

    for (int kb = 0; kb < 2 * HID; kb += 16) {
#pragma unroll
        for (int r = 0; r < 4; r++) {
            int i = tid + r * 256;
            int m = i / 16, k = i % 16;
            int kg = kb + k;
            // 16-chunks never straddle 256, but keep the general form
            float t, lm1;
            if (kg < HID) { t = g_tm[(size_t)(bm + m) * HID + kg];      lm1 = t - 1.0f; }
            else          { t = g_tm[(size_t)(bm + m) * HID + kg - HID]; lm1 = -t; }
            As[k][m] = lm1;
        }
#pragma unroll
        for (int r = 0; r < 4; r++) {
            int i = tid + r * 256;
            int k = i / 64, n = i % 64;
            Bs[k][n] = g_incT[(size_t)(kb + k) * NCL + bn + n];
        }
        __syncthreads();
#pragma unroll
        for (int kk = 0; kk < 16; kk++) {
            float4 a4 = *(const float4*)&As[kk][ty * 4];
            float4 b4 = *(const float4*)&Bs[kk][tx * 4];
            float av[4] = {a4.x, a4.y, a4.z, a4.w};
            float bv[4] = {b4.x, b4.y, b4.z, b4.w};
#pragma unroll
            for (int i = 0; i < 4; i++)
#pragma unroll
                for (int j = 0; j < 4; j++)
                    acc[i][j] = fminf(acc[i][j], fmaf(bv[j], av[i], 1.0f));
        }
        __syncthreads();
    }
#pragma unroll
    for (int i = 0; i < 4; i++) {
        int m = bm + ty * 4 + i;
#pragma unroll
        for (int j = 0; j < 4; j++) {
            int n = bn + tx * 4 + j;
            g_cl[(size_t)m * NCL + n] = (acc[i][j] > 0.5f) ? 1.0f : 0.0f;  // STE forward = hard
        }
    }
}

// ---------------- copy clauses to output + mean summary ------------------
__global__ void clause_out_kernel(float* __restrict__ out_cl, float* __restrict__ out_sum) {
    __shared__ float sm[256];
    int r = blockIdx.x;   // window 0..1567
    int t = threadIdx.x;  // clause 0..255
    float v = g_cl[(size_t)r * NCL + t];
    out_cl[(size_t)r * NCL + t] = v;
    sm[t] = v;
    __syncthreads();
    for (int s = 128; s > 0; s >>= 1) {
        if (t < s) sm[t] += sm[t + s];
        __syncthreads();
    }
    if (t == 0) out_sum[r] = sm[0] * (1.0f / NCL);
}

// ---------------- final: window reverse + roll(+2,+2) + gate + residual ---
__global__ void final_kernel(const float* __restrict__ x, const float* __restrict__ gate,
                             float* __restrict__ out) {
    int idx = blockIdx.x * blockDim.x + threadIdx.x;
    if (idx >= B_ * H_ * W_ * (C_ / 4)) return;
    int c4 = idx % (C_ / 4);
    int p  = idx / (C_ / 4);
    int w  = p % W_;
    int h  = (p / W_) % H_;
    int b  = p / (H_ * W_);
    int hs = (h + H_ - 2) % H_;
    int vs = (w + W_ - 2) % W_;
    int row = b * (NWH * NWH) + (hs >> 2) * NWH + (vs >> 2);
    int off = row * IND + ((hs & 3) * 4 + (vs & 3)) * C_ + c4 * 4;
    float4 m  = *(const float4*)&g_feat[off];
    float4 xv = *(const float4*)(x + (size_t)p * C_ + c4 * 4);
    float g   = sigmoidf_(gate[0]);
    float4 o;
    o.x = xv.x + g * m.x + (1.0f - g) * sigmoidf_(m.x);
    o.y = xv.y + g * m.y + (1.0f - g) * sigmoidf_(m.y);
    o.z = xv.z + g * m.z + (1.0f - g) * sigmoidf_(m.z);
    o.w = xv.w + g * m.w + (1.0f - g) * sigmoidf_(m.w);
    *(float4*)(out + (size_t)p * C_ + c4 * 4) = o;
}

// ---------------- host launcher -----------------------------------------
static float* sym_addr(const void* sym) {
    void* p = nullptr;
    cudaGetSymbolAddress(&p, sym);
    return (float*)p;
}

extern "C" void kernel_launch(void* const* d_in, const int* in_sizes, int n_in,
                              void* d_out, int out_size) {
    const float* x      = (const float*)d_in[0];
    const float* gamma  = (const float*)d_in[1];
    const float* beta   = (const float*)d_in[2];
    const float* W1     = (const float*)d_in[3];
    const float* b1     = (const float*)d_in[4];
    const float* inc_w  = (const float*)d_in[5];
    const float* vote_w = (const float*)d_in[6];
    const float* W2     = (const float*)d_in[7];
    const float* b2     = (const float*)d_in[8];
    const float* gate   = (const float*)d_in[9];

    float* out     = (float*)d_out;
    float* out_cl  = out + (size_t)B_ * H_ * W_ * C_;  // 4,816,896
    float* out_sum = out_cl + (size_t)BW * NCL;        // +401,408

    float* p_win    = sym_addr(g_win);
    float* p_tmpart = sym_addr(g_tm_part);
    float* p_cl     = sym_addr(g_cl);
    float* p_logits = sym_addr(g_logits);
    float* p_feat   = sym_addr(g_feat);

    // 1) LN + roll + partition  (25088 pixels, 1 warp each)
    ln_partition_kernel<<<3136, 256>>>(x, gamma, beta);
    // 2) include-mask transpose
    pack_inc_kernel<<<(2 * HID * NCL + 255) / 256, 256>>>(inc_w);
    // 3) GEMM1 split-K=3: partials = win @ W1   (M=1600,N=256,K=3072)
    gemm_kernel<64, 64, 16, 2><<<dim3(HID / 64, MPAD / 64, KSPLIT), 256>>>(
        p_win, W1, nullptr, p_tmpart, HID, IND, IND / KSPLIT, MPAD * HID, 0.f);
    // 4) combine partials + b1 + sigmoid -> g_tm
    combine_tm_kernel<<<(MPAD * HID) / 256, 256>>>(b1);
    // 5) fuzzy clauses (min-GEMM over 512 literals, hard threshold)
    clause_kernel<<<dim3(NCL / 64, MPAD / 64), 256>>>();
    // 6) clauses out + summary
    clause_out_kernel<<<BW, 256>>>(out_cl, out_sum);
    // 7) logits = clauses @ vote_w / 16   (M=1600,N=192,K=256)
    gemm_kernel<64, 64, 16, 1><<<dim3(C_ / 64, MPAD / 64, 1), 256>>>(
        p_cl, vote_w, nullptr, p_logits, C_, NCL, NCL, 0, 0.0625f);
    // 8) feat = sigmoid(logits @ W2 + b2)  (M=1600,N=3072,K=192)
    gemm_kernel<64, 64, 16, 0><<<dim3(IND / 64, MPAD / 64, 1), 256>>>(
        p_logits, W2, b2, p_feat, IND, C_, C_, 0, 0.f);
    // 9) reverse + roll + gate blend + residual
    final_kernel<<<(B_ * H_ * W_ * (C_ / 4)) / 256, 256>>>(x, gate, out);
}

// round 4
// speedup vs baseline: 2.5781x; 2.5781x over previous
#include <cuda_runtime.h>
#include <cuda_bf16.h>
#include <cstdint>

// ---------------- problem constants ----------------
#define B_    8
#define H_    56
#define W_    56
#define C_    192
#define NWH   14            // windows per side (56/4)
#define BW    1568          // total windows
#define MP    1664          // padded window rows = 13 * 128
#define IND   3072          // 4*4*192
#define HID   256
#define NCL   256
#define KSPL  8             // GEMM1 split-K

// ---------------- scratch (__device__ globals, zero-initialized) ----------
__device__ __nv_bfloat16 g_win[MP * IND];        // LN'd windows, bf16
__device__ __nv_bfloat16 g_W1T[HID * IND];       // W1^T  [256][3072]
__device__ __nv_bfloat16 g_W2T[IND * C_];        // W2^T  [3072][192]
__device__ __nv_bfloat16 g_vwT[256 * NCL];       // vote^T [256 rows (192 valid, rest stay 0)][256]
__device__ float         g_part[KSPL * MP * HID];// GEMM1 split-K partials
__device__ uint32_t      g_incb[16 * NCL];       // include bits [16 words][256 clauses]
__device__ uint32_t      g_litb[MP * 16];        // literal bits per window
__device__ __nv_bfloat16 g_clb[MP * NCL];        // clauses (0/1) bf16
__device__ __nv_bfloat16 g_logb[MP * C_];        // logits bf16
__device__ float         g_feat[MP * IND];       // sigmoid(logits@W2+b2)

__device__ __forceinline__ float sigmoidf_(float x) { return 1.0f / (1.0f + __expf(-x)); }

__device__ __forceinline__ uint32_t s2u(const void* p) {
    uint32_t a;
    asm("{ .reg .u64 t; cvta.to.shared.u64 t, %1; cvt.u32.u64 %0, t; }" : "=r"(a) : "l"(p));
    return a;
}

// ---------------- K1: LayerNorm + roll(-2,-2) + window partition -> bf16 ------
__global__ void ln_partition_kernel(const float* __restrict__ x,
                                    const float* __restrict__ gamma,
                                    const float* __restrict__ beta) {
    int gwarp = (blockIdx.x * blockDim.x + threadIdx.x) >> 5;
    int lane  = threadIdx.x & 31;
    if (gwarp >= B_ * H_ * W_) return;
    const float* xr = x + (size_t)gwarp * C_;
    float v[6];
    float s = 0.f, ss = 0.f;
#pragma unroll
    for (int k = 0; k < 6; k++) {
        v[k] = xr[lane + 32 * k];
        s += v[k]; ss += v[k] * v[k];
    }
#pragma unroll
    for (int o = 16; o > 0; o >>= 1) {
        s  += __shfl_xor_sync(0xffffffffu, s, o);
        ss += __shfl_xor_sync(0xffffffffu, ss, o);
    }
    float mean = s * (1.0f / C_);
    float var  = ss * (1.0f / C_) - mean * mean;
    float inv  = rsqrtf(var + 1e-5f);

    int p = gwarp;
    int w = p % W_;
    int h = (p / W_) % H_;
    int b = p / (H_ * W_);
    int hr = (h + H_ - 2) % H_;
    int wr = (w + W_ - 2) % W_;
    int row  = b * (NWH * NWH) + (hr >> 2) * NWH + (wr >> 2);
    size_t base = (size_t)row * IND + ((hr & 3) * 4 + (wr & 3)) * C_;
#pragma unroll
    for (int k = 0; k < 6; k++) {
        int c = lane + 32 * k;
        g_win[base + c] = __float2bfloat16_rn((v[k] - mean) * inv * gamma[c] + beta[c]);
    }
}

// ---------------- weight transposes (fp32 -> bf16, [N][K] layout) -------------
__global__ void trW1_kernel(const float* __restrict__ W1) {   // [3072][256] -> [256][3072]
    int t = blockIdx.x * blockDim.x + threadIdx.x;
    int k = t >> 8, n = t & 255;
    g_W1T[(size_t)n * IND + k] = __float2bfloat16_rn(W1[t]);
}
__global__ void trW2_kernel(const float* __restrict__ W2) {   // [192][3072] -> [3072][192]
    int t = blockIdx.x * blockDim.x + threadIdx.x;
    int k = t / IND, n = t % IND;
    g_W2T[(size_t)n * C_ + k] = __float2bfloat16_rn(W2[t]);
}
__global__ void trVote_kernel(const float* __restrict__ vw) { // [256][192] -> [192(pad256)][256]
    int t = blockIdx.x * blockDim.x + threadIdx.x;
    int k = t / C_, n = t % C_;
    g_vwT[(size_t)n * NCL + k] = __float2bfloat16_rn(vw[t]);
}

// ---------------- include-mask bitpack:  inc = (inc_w > 0) -------------------
__global__ void pack_inc_kernel(const float* __restrict__ inc_w) {
    int g  = blockIdx.x * blockDim.x + threadIdx.x;  // 131072 = 256 cl * 512 j
    int cl = g >> 9, j = g & 511;
    bool v = inc_w[(size_t)cl * 512 + j] > 0.0f;
    uint32_t m = __ballot_sync(0xffffffffu, v);
    if ((j & 31) == 0) g_incb[(j >> 5) * NCL + cl] = m;
}

// ---------------- bf16 mma.sync GEMM: D[m][n] = sum_k A[m][k]*B[n][k] --------
// 128x128 block tile, BK=32, 8 warps, each warp 64x32 via m16n8k16.
// EPI 0: sigmoid(acc + bias[col]) -> fp32 Cf
// EPI 1: acc*scale -> bf16 Cb (guard col < nValid)
// EPI 2: raw fp32 partial -> Cf + z*zStride
template <int EPI>
__global__ void __launch_bounds__(256)
mma_gemm(const __nv_bfloat16* __restrict__ A, int lda,
         const __nv_bfloat16* __restrict__ Bm, int ldb,
         const float* __restrict__ bias, float scale,
         float* __restrict__ Cf, __nv_bfloat16* __restrict__ Cb,
         int ldc, int nValid, int kPerZ, int zStride) {
    __shared__ __nv_bfloat16 sA[128][40];
    __shared__ __nv_bfloat16 sB[128][40];
    int tid = threadIdx.x, wid = tid >> 5, lane = tid & 31;
    int bm = blockIdx.y * 128, bn = blockIdx.x * 128;
    int k0 = blockIdx.z * kPerZ;
    if (EPI == 2) Cf += (size_t)blockIdx.z * zStride;

    int wm = (wid & 1) * 64;      // warp M offset within block
    int wn = (wid >> 1) * 32;     // warp N offset

    float c[4][4][4];
#pragma unroll
    for (int i = 0; i < 4; i++)
#pragma unroll
        for (int j = 0; j < 4; j++)
#pragma unroll
            for (int q = 0; q < 4; q++) c[i][j][q] = 0.f;

    for (int kb = k0; kb < k0 + kPerZ; kb += 32) {
        // stage tiles: 128 rows x 32 cols each (512 uint4 per tile, 2 per thread)
#pragma unroll
        for (int r = 0; r < 2; r++) {
            int i = tid + r * 256;
            int row = i >> 2, ch = i & 3;
            *(uint4*)&sA[row][ch * 8] =
                *(const uint4*)(A + (size_t)(bm + row) * lda + kb + ch * 8);
            *(uint4*)&sB[row][ch * 8] =
                *(const uint4*)(Bm + (size_t)(bn + row) * ldb + kb + ch * 8);
        }
        __syncthreads();
#pragma unroll
        for (int ks = 0; ks < 2; ks++) {
            int kk = ks * 16;
            uint32_t a[4][4], b[4][2];
#pragma unroll
            for (int mi = 0; mi < 4; mi++) {
                uint32_t addr = s2u(&sA[wm + mi * 16 + (lane & 15)][kk + (lane >> 4) * 8]);
                asm volatile("ldmatrix.sync.aligned.m8n8.x4.shared.b16 {%0,%1,%2,%3}, [%4];"
                             : "=r"(a[mi][0]), "=r"(a[mi][1]), "=r"(a[mi][2]), "=r"(a[mi][3])
                             : "r"(addr));
            }
#pragma unroll
            for (int ni = 0; ni < 4; ni++) {
                int l = lane & 15;
                uint32_t addr = s2u(&sB[wn + ni * 8 + (l & 7)][kk + (l >> 3) * 8]);
                asm volatile("ldmatrix.sync.aligned.m8n8.x2.shared.b16 {%0,%1}, [%2];"
                             : "=r"(b[ni][0]), "=r"(b[ni][1]) : "r"(addr));
            }
#pragma unroll
            for (int mi = 0; mi < 4; mi++)
#pragma unroll
                for (int ni = 0; ni < 4; ni++)
                    asm volatile(
                        "mma.sync.aligned.m16n8k16.row.col.f32.bf16.bf16.f32 "
                        "{%0,%1,%2,%3}, {%4,%5,%6,%7}, {%8,%9}, {%0,%1,%2,%3};"
                        : "+f"(c[mi][ni][0]), "+f"(c[mi][ni][1]),
                          "+f"(c[mi][ni][2]), "+f"(c[mi][ni][3])
                        : "r"(a[mi][0]), "r"(a[mi][1]), "r"(a[mi][2]), "r"(a[mi][3]),
                          "r"(b[ni][0]), "r"(b[ni][1]));
        }
        __syncthreads();
    }

    // epilogue: fragment (mi,ni): rows wm+mi*16+lane/4 (+8), cols wn+ni*8+(lane%4)*2
#pragma unroll
    for (int mi = 0; mi < 4; mi++) {
        int row = bm + wm + mi * 16 + (lane >> 2);
#pragma unroll
        for (int ni = 0; ni < 4; ni++) {
            int col = bn + wn + ni * 8 + (lane & 3) * 2;
            float v0 = c[mi][ni][0], v1 = c[mi][ni][1];
            float v2 = c[mi][ni][2], v3 = c[mi][ni][3];
            if (EPI == 0) {
                float b0 = bias[col], b1 = bias[col + 1];
                float2 o0 = make_float2(sigmoidf_(v0 + b0), sigmoidf_(v1 + b1));
                float2 o1 = make_float2(sigmoidf_(v2 + b0), sigmoidf_(v3 + b1));
                *(float2*)(Cf + (size_t)row * ldc + col) = o0;
                *(float2*)(Cf + (size_t)(row + 8) * ldc + col) = o1;
            } else if (EPI == 1) {
                if (col < nValid) {
                    *(__nv_bfloat162*)(Cb + (size_t)row * ldc + col) =
                        __floats2bfloat162_rn(v0 * scale, v1 * scale);
                    *(__nv_bfloat162*)(Cb + (size_t)(row + 8) * ldc + col) =
                        __floats2bfloat162_rn(v2 * scale, v3 * scale);
                }
            } else {
                *(float2*)(Cf + (size_t)row * ldc + col) = make_float2(v0, v1);
                *(float2*)(Cf + (size_t)(row + 8) * ldc + col) = make_float2(v2, v3);
            }
        }
    }
}

// ---------------- combine split-K partials -> literal bits --------------------
// tm > 0.5  <=>  preact > 0 ; words 0-7 = (s>0), words 8-15 = (s<0)
__global__ void combine_bits_kernel(const float* __restrict__ b1) {
    int row = blockIdx.x;       // 0..MP-1
    int c   = threadIdx.x;      // 0..255
    float s = b1[c];
#pragma unroll
    for (int z = 0; z < KSPL; z++) s += g_part[(size_t)z * MP * HID + (size_t)row * HID + c];
    uint32_t mp = __ballot_sync(0xffffffffu, s > 0.0f);
    uint32_t mn = __ballot_sync(0xffffffffu, s < 0.0f);
    if ((c & 31) == 0) {
        g_litb[row * 16 + (c >> 5)]     = mp;
        g_litb[row * 16 + 8 + (c >> 5)] = mn;
    }
}

// ---------------- clause bits + outputs + summary -----------------------------
__global__ void clause_kernel(float* __restrict__ out_cl, float* __restrict__ out_sum) {
    __shared__ uint32_t slit[16];
    __shared__ float red[256];
    int row = blockIdx.x;       // 0..MP-1
    int cl  = threadIdx.x;      // 0..255
    if (cl < 16) slit[cl] = g_litb[row * 16 + cl];
    __syncthreads();
    uint32_t viol = 0;
#pragma unroll
    for (int i = 0; i < 16; i++) viol |= g_incb[i * NCL + cl] & ~slit[i];
    float cv = (viol == 0u) ? 1.0f : 0.0f;
    g_clb[(size_t)row * NCL + cl] = __float2bfloat16_rn(cv);
    red[cl] = cv;
    if (row < BW) out_cl[(size_t)row * NCL + cl] = cv;
    __syncthreads();
    for (int s = 128; s > 0; s >>= 1) {
        if (cl < s) red[cl] += red[cl + s];
        __syncthreads();
    }
    if (cl == 0 && row < BW) out_sum[row] = red[0] * (1.0f / NCL);
}

// ---------------- final: window reverse + roll(+2,+2) + gate + residual -------
__global__ void final_kernel(const float* __restrict__ x, const float* __restrict__ gate,
                             float* __restrict__ out) {
    int idx = blockIdx.x * blockDim.x + threadIdx.x;
    if (idx >= B_ * H_ * W_ * (C_ / 4)) return;
    int c4 = idx % (C_ / 4);
    int p  = idx / (C_ / 4);
    int w  = p % W_;
    int h  = (p / W_) % H_;
    int b  = p / (H_ * W_);
    int hs = (h + H_ - 2) % H_;
    int vs = (w + W_ - 2) % W_;
    int row = b * (NWH * NWH) + (hs >> 2) * NWH + (vs >> 2);
    size_t off = (size_t)row * IND + ((hs & 3) * 4 + (vs & 3)) * C_ + c4 * 4;
    float4 m  = *(const float4*)&g_feat[off];
    float4 xv = *(const float4*)(x + (size_t)p * C_ + c4 * 4);
    float g   = sigmoidf_(gate[0]);
    float4 o;
    o.x = xv.x + g * m.x + (1.0f - g) * sigmoidf_(m.x);
    o.y = xv.y + g * m.y + (1.0f - g) * sigmoidf_(m.y);
    o.z = xv.z + g * m.z + (1.0f - g) * sigmoidf_(m.z);
    o.w = xv.w + g * m.w + (1.0f - g) * sigmoidf_(m.w);
    *(float4*)(out + (size_t)p * C_ + c4 * 4) = o;
}

// ---------------- host launcher -----------------------------------------------
static void* sym_addr(const void* sym) {
    void* p = nullptr;
    cudaGetSymbolAddress(&p, sym);
    return p;
}

extern "C" void kernel_launch(void* const* d_in, const int* in_sizes, int n_in,
                              void* d_out, int out_size) {
    const float* x      = (const float*)d_in[0];
    const float* gamma  = (const float*)d_in[1];
    const float* beta   = (const float*)d_in[2];
    const float* W1     = (const float*)d_in[3];
    const float* b1     = (const float*)d_in[4];
    const float* inc_w  = (const float*)d_in[5];
    const float* vote_w = (const float*)d_in[6];
    const float* W2     = (const float*)d_in[7];
    const float* b2     = (const float*)d_in[8];
    const float* gate   = (const float*)d_in[9];

    float* out     = (float*)d_out;
    float* out_cl  = out + (size_t)B_ * H_ * W_ * C_;
    float* out_sum = out_cl + (size_t)BW * NCL;

    __nv_bfloat16* p_win  = (__nv_bfloat16*)sym_addr(g_win);
    __nv_bfloat16* p_W1T  = (__nv_bfloat16*)sym_addr(g_W1T);
    __nv_bfloat16* p_W2T  = (__nv_bfloat16*)sym_addr(g_W2T);
    __nv_bfloat16* p_vwT  = (__nv_bfloat16*)sym_addr(g_vwT);
    __nv_bfloat16* p_clb  = (__nv_bfloat16*)sym_addr(g_clb);
    __nv_bfloat16* p_logb = (__nv_bfloat16*)sym_addr(g_logb);
    float*         p_part = (float*)sym_addr(g_part);
    float*         p_feat = (float*)sym_addr(g_feat);

    // 1) LN + roll + window partition -> bf16
    ln_partition_kernel<<<3136, 256>>>(x, gamma, beta);
    // 2) weight transposes + include bitpack (independent of 1)
    trW1_kernel<<<3072, 256>>>(W1);
    trW2_kernel<<<2304, 256>>>(W2);
    trVote_kernel<<<192, 256>>>(vote_w);
    pack_inc_kernel<<<512, 256>>>(inc_w);
    // 3) GEMM1 (mma.sync bf16, split-K=8): partials = win @ W1
    mma_gemm<2><<<dim3(2, 13, KSPL), 256>>>(p_win, IND, p_W1T, IND, nullptr, 0.f,
                                            p_part, nullptr, HID, HID, IND / KSPL, MP * HID);
    // 4) combine partials + b1 -> literal bits
    combine_bits_kernel<<<MP, 256>>>(b1);
    // 5) clause bits + clause/summary outputs
    clause_kernel<<<MP, 256>>>(out_cl, out_sum);
    // 6) GEMM2: logits = clauses @ vote_w / 16 -> bf16
    mma_gemm<1><<<dim3(2, 13, 1), 256>>>(p_clb, NCL, p_vwT, NCL, nullptr, 0.0625f,
                                         nullptr, p_logb, C_, C_, NCL, 0);
    // 7) GEMM3: feat = sigmoid(logits @ W2 + b2)
    mma_gemm<0><<<dim3(24, 13, 1), 256>>>(p_logb, C_, p_W2T, C_, b2, 0.f,
                                          p_feat, nullptr, IND, IND, C_, 0);
    // 8) window reverse + roll + gate + residual
    final_kernel<<<(B_ * H_ * W_ * (C_ / 4)) / 256, 256>>>(x, gate, out);
}

// round 7
// speedup vs baseline: 2.9227x; 1.1337x over previous
#include <cuda_runtime.h>
#include <cuda_bf16.h>
#include <cstdint>

// ---------------- problem constants ----------------
#define B_    8
#define H_    56
#define W_    56
#define C_    192
#define NWH   14            // windows per side (56/4)
#define BW    1568          // total windows
#define MP    1664          // padded window rows = 13 * 128
#define IND   3072          // 4*4*192
#define HID   256
#define NCL   256
#define KSPL  8             // GEMM1 split-K

// ---------------- scratch (__device__ globals, zero-initialized) ----------
__device__ __nv_bfloat16 g_win[MP * IND];        // LN'd windows, bf16
__device__ __nv_bfloat16 g_W1T[HID * IND];       // W1^T  [256][3072]
__device__ __nv_bfloat16 g_W2T[IND * C_];        // W2^T  [3072][192]
__device__ __nv_bfloat16 g_vwT[256 * NCL];       // vote^T [256 rows (192 valid)][256]
__device__ float         g_part[KSPL * MP * HID];// GEMM1 split-K partials
__device__ uint32_t      g_incb[16 * NCL];       // include bits [16 words][256 clauses]
__device__ __nv_bfloat16 g_clb[MP * NCL];        // clauses (0/1) bf16
__device__ __nv_bfloat16 g_logb[MP * C_];        // logits bf16

__device__ __forceinline__ float sigmoidf_(float x) { return 1.0f / (1.0f + __expf(-x)); }

__device__ __forceinline__ uint32_t s2u(const void* p) {
    uint32_t a;
    asm("{ .reg .u64 t; cvta.to.shared.u64 t, %1; cvt.u32.u64 %0, t; }" : "=r"(a) : "l"(p));
    return a;
}
#define CP_ASYNC16(dst, src) \
    asm volatile("cp.async.cg.shared.global [%0], [%1], 16;" :: "r"(dst), "l"(src))
#define CP_COMMIT() asm volatile("cp.async.commit_group;")
#define CP_WAIT(n)  asm volatile("cp.async.wait_group %0;" :: "n"(n))

// ---------------- K1: LayerNorm + roll(-2,-2) + window partition -> bf16 ------
__global__ void ln_partition_kernel(const float* __restrict__ x,
                                    const float* __restrict__ gamma,
                                    const float* __restrict__ beta) {
    int gwarp = (blockIdx.x * blockDim.x + threadIdx.x) >> 5;
    int lane  = threadIdx.x & 31;
    if (gwarp >= B_ * H_ * W_) return;
    const float* xr = x + (size_t)gwarp * C_;
    float v[6];
    float s = 0.f, ss = 0.f;
#pragma unroll
    for (int k = 0; k < 6; k++) {
        v[k] = xr[lane + 32 * k];
        s += v[k]; ss += v[k] * v[k];
    }
#pragma unroll
    for (int o = 16; o > 0; o >>= 1) {
        s  += __shfl_xor_sync(0xffffffffu, s, o);
        ss += __shfl_xor_sync(0xffffffffu, ss, o);
    }
    float mean = s * (1.0f / C_);
    float var  = ss * (1.0f / C_) - mean * mean;
    float inv  = rsqrtf(var + 1e-5f);

    int p = gwarp;
    int w = p % W_;
    int h = (p / W_) % H_;
    int b = p / (H_ * W_);
    int hr = (h + H_ - 2) % H_;
    int wr = (w + W_ - 2) % W_;
    int row  = b * (NWH * NWH) + (hr >> 2) * NWH + (wr >> 2);
    size_t base = (size_t)row * IND + ((hr & 3) * 4 + (wr & 3)) * C_;
#pragma unroll
    for (int k = 0; k < 6; k++) {
        int c = lane + 32 * k;
        g_win[base + c] = __float2bfloat16_rn((v[k] - mean) * inv * gamma[c] + beta[c]);
    }
}

// ---------------- fused prep: W1^T, W2^T, vote^T, include bitpack -------------
#define SEG1 786432            // trW1:  3072*256
#define SEG2 1376256           // +trW2: 192*3072
#define SEG3 1425408           // +trVote: 256*192
#define SEGT 1556480           // +pack_inc: 256*512
__global__ void prep_fused_kernel(const float* __restrict__ W1,
                                  const float* __restrict__ W2,
                                  const float* __restrict__ vw,
                                  const float* __restrict__ inc_w) {
    int t = blockIdx.x * blockDim.x + threadIdx.x;
    if (t < SEG1) {                       // [3072][256] -> [256][3072]
        int k = t >> 8, n = t & 255;
        g_W1T[(size_t)n * IND + k] = __float2bfloat16_rn(W1[t]);
    } else if (t < SEG2) {                // [192][3072] -> [3072][192]
        int u = t - SEG1;
        int k = u / IND, n = u % IND;
        g_W2T[(size_t)n * C_ + k] = __float2bfloat16_rn(W2[u]);
    } else if (t < SEG3) {                // [256][192] -> [192(pad256)][256]
        int u = t - SEG2;
        int k = u / C_, n = u % C_;
        g_vwT[(size_t)n * NCL + k] = __float2bfloat16_rn(vw[u]);
    } else {                              // include bits: inc = (inc_w > 0)
        int u  = t - SEG3;
        int cl = u >> 9, j = u & 511;
        bool v = inc_w[(size_t)cl * 512 + j] > 0.0f;
        uint32_t m = __ballot_sync(0xffffffffu, v);
        if ((j & 31) == 0) g_incb[(j >> 5) * NCL + cl] = m;
    }
}

// ---------------- bf16 mma.sync GEMM, 2-stage cp.async pipeline ---------------
// D[m][n] = sum_k A[m][k]*B[n][k];  128x128 tile, BK=32, 8 warps x (64x32).
// EPI 0: GEMM3 fused final epilogue (window reverse + roll + gate + residual)
// EPI 1: acc*scale -> bf16 Cb (guard col < nValid)
// EPI 2: raw fp32 partial -> Cf + z*zStride
template <int EPI>
__global__ void __launch_bounds__(256)
mma_gemm(const __nv_bfloat16* __restrict__ A, int lda,
         const __nv_bfloat16* __restrict__ Bm, int ldb,
         const float* __restrict__ bias, float scale,
         float* __restrict__ Cf, __nv_bfloat16* __restrict__ Cb,
         int ldc, int nValid, int kPerZ, int zStride,
         const float* __restrict__ xres, const float* __restrict__ gate,
         float* __restrict__ out) {
    __shared__ __nv_bfloat16 sA[2][128][40];
    __shared__ __nv_bfloat16 sB[2][128][40];
    int tid = threadIdx.x, wid = tid >> 5, lane = tid & 31;
    int bm = blockIdx.y * 128, bn = blockIdx.x * 128;
    int k0 = blockIdx.z * kPerZ;
    if (EPI == 2) Cf += (size_t)blockIdx.z * zStride;

    int wm = (wid & 1) * 64;
    int wn = (wid >> 1) * 32;

    // staging: 128 rows x 32 cols = 512 16B-chunks per tile; 2 chunk-slots/thread
    int i0 = tid,        r0 = i0 >> 2, c0 = (i0 & 3) * 8;
    int i1 = tid + 256,  r1 = i1 >> 2, c1 = (i1 & 3) * 8;
    const __nv_bfloat16* pA0 = A + (size_t)(bm + r0) * lda + c0;
    const __nv_bfloat16* pA1 = A + (size_t)(bm + r1) * lda + c1;
    const __nv_bfloat16* pB0 = Bm + (size_t)(bn + r0) * ldb + c0;
    const __nv_bfloat16* pB1 = Bm + (size_t)(bn + r1) * ldb + c1;

    float c[4][4][4];
#pragma unroll
    for (int i = 0; i < 4; i++)
#pragma unroll
        for (int j = 0; j < 4; j++)
#pragma unroll
            for (int q = 0; q < 4; q++) c[i][j][q] = 0.f;

    int iters = kPerZ >> 5;
    // prologue: stage 0
    CP_ASYNC16(s2u(&sA[0][r0][c0]), pA0 + k0);
    CP_ASYNC16(s2u(&sA[0][r1][c1]), pA1 + k0);
    CP_ASYNC16(s2u(&sB[0][r0][c0]), pB0 + k0);
    CP_ASYNC16(s2u(&sB[0][r1][c1]), pB1 + k0);
    CP_COMMIT();

    for (int it = 0; it < iters; ++it) {
        if (it + 1 < iters) {
            int s = (it + 1) & 1;
            int kb = k0 + (it + 1) * 32;
            CP_ASYNC16(s2u(&sA[s][r0][c0]), pA0 + kb);
            CP_ASYNC16(s2u(&sA[s][r1][c1]), pA1 + kb);
            CP_ASYNC16(s2u(&sB[s][r0][c0]), pB0 + kb);
            CP_ASYNC16(s2u(&sB[s][r1][c1]), pB1 + kb);
            CP_COMMIT();
            CP_WAIT(1);
        } else {
            CP_WAIT(0);
        }
        __syncthreads();
        int cs = it & 1;
#pragma unroll
        for (int ks = 0; ks < 2; ks++) {
            int kk = ks * 16;
            uint32_t a[4][4], b[4][2];
#pragma unroll
            for (int mi = 0; mi < 4; mi++) {
                uint32_t addr = s2u(&sA[cs][wm + mi * 16 + (lane & 15)][kk + (lane >> 4) * 8]);
                asm volatile("ldmatrix.sync.aligned.m8n8.x4.shared.b16 {%0,%1,%2,%3}, [%4];"
                             : "=r"(a[mi][0]), "=r"(a[mi][1]), "=r"(a[mi][2]), "=r"(a[mi][3])
                             : "r"(addr));
            }
#pragma unroll
            for (int ni = 0; ni < 4; ni++) {
                int l = lane & 15;
                uint32_t addr = s2u(&sB[cs][wn + ni * 8 + (l & 7)][kk + (l >> 3) * 8]);
                asm volatile("ldmatrix.sync.aligned.m8n8.x2.shared.b16 {%0,%1}, [%2];"
                             : "=r"(b[ni][0]), "=r"(b[ni][1]) : "r"(addr));
            }
#pragma unroll
            for (int mi = 0; mi < 4; mi++)
#pragma unroll
                for (int ni = 0; ni < 4; ni++)
                    asm volatile(
                        "mma.sync.aligned.m16n8k16.row.col.f32.bf16.bf16.f32 "
                        "{%0,%1,%2,%3}, {%4,%5,%6,%7}, {%8,%9}, {%0,%1,%2,%3};"
                        : "+f"(c[mi][ni][0]), "+f"(c[mi][ni][1]),
                          "+f"(c[mi][ni][2]), "+f"(c[mi][ni][3])
                        : "r"(a[mi][0]), "r"(a[mi][1]), "r"(a[mi][2]), "r"(a[mi][3]),
                          "r"(b[ni][0]), "r"(b[ni][1]));
        }
        __syncthreads();
    }

    // ---------------- epilogues ----------------
    if (EPI == 0) {
        float g = sigmoidf_(gate[0]);
#pragma unroll
        for (int mi = 0; mi < 4; mi++) {
            int row0 = bm + wm + mi * 16 + (lane >> 2);
#pragma unroll
            for (int rr = 0; rr < 2; rr++) {
                int row = row0 + rr * 8;           // window index
                if (row >= BW) continue;
                int b   = row / (NWH * NWH);
                int r2  = row % (NWH * NWH);
                int wh  = r2 / NWH, ww = r2 % NWH;
#pragma unroll
                for (int ni = 0; ni < 4; ni++) {
                    int col = bn + wn + ni * 8 + (lane & 3) * 2;
                    int wpos = col / C_;
                    int ch   = col - wpos * C_;
                    int hr = wh * 4 + (wpos >> 2);
                    int wr = ww * 4 + (wpos & 3);
                    int h = hr + 2; if (h >= H_) h -= H_;
                    int w = wr + 2; if (w >= W_) w -= W_;
                    size_t pix = ((size_t)(b * H_ + h) * W_ + w) * C_ + ch;
                    float v0 = c[mi][ni][rr * 2 + 0];
                    float v1 = c[mi][ni][rr * 2 + 1];
                    float m0 = sigmoidf_(v0 + bias[col]);
                    float m1 = sigmoidf_(v1 + bias[col + 1]);
                    float2 xv = *(const float2*)(xres + pix);
                    float2 o;
                    o.x = xv.x + g * m0 + (1.0f - g) * sigmoidf_(m0);
                    o.y = xv.y + g * m1 + (1.0f - g) * sigmoidf_(m1);
                    *(float2*)(out + pix) = o;
                }
            }
        }
    } else {
#pragma unroll
        for (int mi = 0; mi < 4; mi++) {
            int row = bm + wm + mi * 16 + (lane >> 2);
#pragma unroll
            for (int ni = 0; ni < 4; ni++) {
                int col = bn + wn + ni * 8 + (lane & 3) * 2;
                float v0 = c[mi][ni][0], v1 = c[mi][ni][1];
                float v2 = c[mi][ni][2], v3 = c[mi][ni][3];
                if (EPI == 1) {
                    if (col < nValid) {
                        *(__nv_bfloat162*)(Cb + (size_t)row * ldc + col) =
                            __floats2bfloat162_rn(v0 * scale, v1 * scale);
                        *(__nv_bfloat162*)(Cb + (size_t)(row + 8) * ldc + col) =
                            __floats2bfloat162_rn(v2 * scale, v3 * scale);
                    }
                } else {
                    *(float2*)(Cf + (size_t)row * ldc + col) = make_float2(v0, v1);
                    *(float2*)(Cf + (size_t)(row + 8) * ldc + col) = make_float2(v2, v3);
                }
            }
        }
    }
}

// ---------------- fused: combine split-K -> literal bits -> clauses ----------
__global__ void combine_clause_kernel(const float* __restrict__ b1,
                                      float* __restrict__ out_cl,
                                      float* __restrict__ out_sum) {
    __shared__ uint32_t slit[16];
    __shared__ float red[256];
    int row = blockIdx.x;       // 0..MP-1
    int c   = threadIdx.x;      // 0..255  (feature, then clause)
    float s = b1[c];
#pragma unroll
    for (int z = 0; z < KSPL; z++) s += g_part[(size_t)z * MP * HID + (size_t)row * HID + c];
    uint32_t mp = __ballot_sync(0xffffffffu, s > 0.0f);
    uint32_t mn = __ballot_sync(0xffffffffu, s < 0.0f);
    if ((c & 31) == 0) {
        slit[c >> 5]       = mp;
        slit[8 + (c >> 5)] = mn;
    }
    __syncthreads();
    uint32_t viol = 0;
#pragma unroll
    for (int i = 0; i < 16; i++) viol |= g_incb[i * NCL + c] & ~slit[i];
    float cv = (viol == 0u) ? 1.0f : 0.0f;
    g_clb[(size_t)row * NCL + c] = __float2bfloat16_rn(cv);
    red[c] = cv;
    if (row < BW) out_cl[(size_t)row * NCL + c] = cv;
    __syncthreads();
    for (int st = 128; st > 0; st >>= 1) {
        if (c < st) red[c] += red[c + st];
        __syncthreads();
    }
    if (c == 0 && row < BW) out_sum[row] = red[0] * (1.0f / NCL);
}

// ---------------- host launcher -----------------------------------------------
static void* sym_addr(const void* sym) {
    void* p = nullptr;
    cudaGetSymbolAddress(&p, sym);
    return p;
}

extern "C" void kernel_launch(void* const* d_in, const int* in_sizes, int n_in,
                              void* d_out, int out_size) {
    const float* x      = (const float*)d_in[0];
    const float* gamma  = (const float*)d_in[1];
    const float* beta   = (const float*)d_in[2];
    const float* W1     = (const float*)d_in[3];
    const float* b1     = (const float*)d_in[4];
    const float* inc_w  = (const float*)d_in[5];
    const float* vote_w = (const float*)d_in[6];
    const float* W2     = (const float*)d_in[7];
    const float* b2     = (const float*)d_in[8];
    const float* gate   = (const float*)d_in[9];

    float* out     = (float*)d_out;
    float* out_cl  = out + (size_t)B_ * H_ * W_ * C_;
    float* out_sum = out_cl + (size_t)BW * NCL;

    __nv_bfloat16* p_win  = (__nv_bfloat16*)sym_addr(g_win);
    __nv_bfloat16* p_W1T  = (__nv_bfloat16*)sym_addr(g_W1T);
    __nv_bfloat16* p_W2T  = (__nv_bfloat16*)sym_addr(g_W2T);
    __nv_bfloat16* p_vwT  = (__nv_bfloat16*)sym_addr(g_vwT);
    __nv_bfloat16* p_clb  = (__nv_bfloat16*)sym_addr(g_clb);
    __nv_bfloat16* p_logb = (__nv_bfloat16*)sym_addr(g_logb);
    float*         p_part = (float*)sym_addr(g_part);

    // 1) LN + roll + window partition -> bf16
    ln_partition_kernel<<<3136, 256>>>(x, gamma, beta);
    // 2) fused prep: weight transposes + include bitpack
    prep_fused_kernel<<<SEGT / 256, 256>>>(W1, W2, vote_w, inc_w);
    // 3) GEMM1 (split-K=8): partials = win @ W1
    mma_gemm<2><<<dim3(2, 13, KSPL), 256>>>(p_win, IND, p_W1T, IND, nullptr, 0.f,
                                            p_part, nullptr, HID, HID, IND / KSPL, MP * HID,
                                            nullptr, nullptr, nullptr);
    // 4) combine partials -> literal bits -> clause bits + outputs
    combine_clause_kernel<<<MP, 256>>>(b1, out_cl, out_sum);
    // 5) GEMM2: logits = clauses @ vote_w / 16 -> bf16
    mma_gemm<1><<<dim3(2, 13, 1), 256>>>(p_clb, NCL, p_vwT, NCL, nullptr, 0.0625f,
                                         nullptr, p_logb, C_, C_, NCL, 0,
                                         nullptr, nullptr, nullptr);
    // 6) GEMM3 + fused final: out = x + blend(sigmoid(logits @ W2 + b2))
    mma_gemm<0><<<dim3(24, 13, 1), 256>>>(p_logb, C_, p_W2T, C_, b2, 0.f,
                                          nullptr, nullptr, IND, IND, C_, 0,
                                          x, gate, out);
}

// round 8
// speedup vs baseline: 3.0334x; 1.0379x over previous
#include <cuda_runtime.h>
#include <cuda_bf16.h>
#include <cstdint>

// ---------------- problem constants ----------------
#define B_    8
#define H_    56
#define W_    56
#define C_    192
#define NWH   14            // windows per side (56/4)
#define BW    1568          // total windows
#define MP    1664          // padded window rows = 13 * 128
#define IND   3072          // 4*4*192
#define HID   256
#define NCL   256
#define KSPL  4             // GEMM1 split-K

// ---------------- scratch (__device__ globals, zero-initialized) ----------
__device__ __nv_bfloat16 g_win[MP * IND];        // LN'd windows, bf16
__device__ __nv_bfloat16 g_W1T[HID * IND];       // W1^T  [256][3072]
__device__ __nv_bfloat16 g_W2T[IND * C_];        // W2^T  [3072][192]
__device__ __nv_bfloat16 g_vwT[256 * NCL];       // vote^T [256 rows (192 valid)][256]
__device__ float         g_part[KSPL * MP * HID];// GEMM1 split-K partials
__device__ uint32_t      g_incb[16 * NCL];       // include bits [16 words][256 clauses]
__device__ __nv_bfloat16 g_clb[MP * NCL];        // clauses (0/1) bf16
__device__ __nv_bfloat16 g_logb[MP * C_];        // logits bf16

__device__ __forceinline__ float sigmoidf_(float x) { return 1.0f / (1.0f + __expf(-x)); }

__device__ __forceinline__ uint32_t s2u(const void* p) {
    uint32_t a;
    asm("{ .reg .u64 t; cvta.to.shared.u64 t, %1; cvt.u32.u64 %0, t; }" : "=r"(a) : "l"(p));
    return a;
}
#define CP_ASYNC16(dst, src) \
    asm volatile("cp.async.cg.shared.global [%0], [%1], 16;" :: "r"(dst), "l"(src))
#define CP_COMMIT() asm volatile("cp.async.commit_group;")
#define CP_WAIT(n)  asm volatile("cp.async.wait_group %0;" :: "n"(n))

// ---------------- K1: LayerNorm + roll(-2,-2) + window partition -> bf16 ------
__global__ void ln_partition_kernel(const float* __restrict__ x,
                                    const float* __restrict__ gamma,
                                    const float* __restrict__ beta) {
    int gwarp = (blockIdx.x * blockDim.x + threadIdx.x) >> 5;
    int lane  = threadIdx.x & 31;
    if (gwarp >= B_ * H_ * W_) return;
    const float* xr = x + (size_t)gwarp * C_;
    float v[6];
    float s = 0.f, ss = 0.f;
#pragma unroll
    for (int k = 0; k < 6; k++) {
        v[k] = xr[lane + 32 * k];
        s += v[k]; ss += v[k] * v[k];
    }
#pragma unroll
    for (int o = 16; o > 0; o >>= 1) {
        s  += __shfl_xor_sync(0xffffffffu, s, o);
        ss += __shfl_xor_sync(0xffffffffu, ss, o);
    }
    float mean = s * (1.0f / C_);
    float var  = ss * (1.0f / C_) - mean * mean;
    float inv  = rsqrtf(var + 1e-5f);

    int p = gwarp;
    int w = p % W_;
    int h = (p / W_) % H_;
    int b = p / (H_ * W_);
    int hr = (h + H_ - 2) % H_;
    int wr = (w + W_ - 2) % W_;
    int row  = b * (NWH * NWH) + (hr >> 2) * NWH + (wr >> 2);
    size_t base = (size_t)row * IND + ((hr & 3) * 4 + (wr & 3)) * C_;
#pragma unroll
    for (int k = 0; k < 6; k++) {
        int c = lane + 32 * k;
        g_win[base + c] = __float2bfloat16_rn((v[k] - mean) * inv * gamma[c] + beta[c]);
    }
}

// ---------------- fused prep: W1^T, W2^T, vote^T, include bitpack -------------
#define SEG1 786432            // trW1:  3072*256
#define SEG2 1376256           // +trW2: 192*3072
#define SEG3 1425408           // +trVote: 256*192
#define SEGT 1556480           // +pack_inc: 256*512
__global__ void prep_fused_kernel(const float* __restrict__ W1,
                                  const float* __restrict__ W2,
                                  const float* __restrict__ vw,
                                  const float* __restrict__ inc_w) {
    int t = blockIdx.x * blockDim.x + threadIdx.x;
    if (t < SEG1) {                       // [3072][256] -> [256][3072]
        int k = t >> 8, n = t & 255;
        g_W1T[(size_t)n * IND + k] = __float2bfloat16_rn(W1[t]);
    } else if (t < SEG2) {                // [192][3072] -> [3072][192]
        int u = t - SEG1;
        int k = u / IND, n = u % IND;
        g_W2T[(size_t)n * C_ + k] = __float2bfloat16_rn(W2[u]);
    } else if (t < SEG3) {                // [256][192] -> [192(pad256)][256]
        int u = t - SEG2;
        int k = u / C_, n = u % C_;
        g_vwT[(size_t)n * NCL + k] = __float2bfloat16_rn(vw[u]);
    } else {                              // include bits: inc = (inc_w > 0)
        int u  = t - SEG3;
        int cl = u >> 9, j = u & 511;
        bool v = inc_w[(size_t)cl * 512 + j] > 0.0f;
        uint32_t m = __ballot_sync(0xffffffffu, v);
        if ((j & 31) == 0) g_incb[(j >> 5) * NCL + cl] = m;
    }
}

// ---------------- bf16 mma.sync GEMM, 2-stage cp.async pipeline ---------------
// D[m][n] = sum_k A[m][k]*B[n][k];  128x128 tile, BK=32, 8 warps x (64x32).
// EPI 0: GEMM3 fused final epilogue (window reverse + roll + gate + residual)
// EPI 1: acc*scale -> bf16 Cb (guard col < nValid)
// EPI 2: raw fp32 partial -> Cf + z*zStride
template <int EPI>
__global__ void __launch_bounds__(256)
mma_gemm(const __nv_bfloat16* __restrict__ A, int lda,
         const __nv_bfloat16* __restrict__ Bm, int ldb,
         const float* __restrict__ bias, float scale,
         float* __restrict__ Cf, __nv_bfloat16* __restrict__ Cb,
         int ldc, int nValid, int kPerZ, int zStride,
         const float* __restrict__ xres, const float* __restrict__ gate,
         float* __restrict__ out) {
    __shared__ __nv_bfloat16 sA[2][128][40];
    __shared__ __nv_bfloat16 sB[2][128][40];
    int tid = threadIdx.x, wid = tid >> 5, lane = tid & 31;
    int bm = blockIdx.y * 128, bn = blockIdx.x * 128;
    int k0 = blockIdx.z * kPerZ;
    if (EPI == 2) Cf += (size_t)blockIdx.z * zStride;

    int wm = (wid & 1) * 64;
    int wn = (wid >> 1) * 32;

    // staging: 128 rows x 32 cols = 512 16B-chunks per tile; 2 chunk-slots/thread
    int i0 = tid,        r0 = i0 >> 2, c0 = (i0 & 3) * 8;
    int i1 = tid + 256,  r1 = i1 >> 2, c1 = (i1 & 3) * 8;
    const __nv_bfloat16* pA0 = A + (size_t)(bm + r0) * lda + c0;
    const __nv_bfloat16* pA1 = A + (size_t)(bm + r1) * lda + c1;
    const __nv_bfloat16* pB0 = Bm + (size_t)(bn + r0) * ldb + c0;
    const __nv_bfloat16* pB1 = Bm + (size_t)(bn + r1) * ldb + c1;

    float c[4][4][4];
#pragma unroll
    for (int i = 0; i < 4; i++)
#pragma unroll
        for (int j = 0; j < 4; j++)
#pragma unroll
            for (int q = 0; q < 4; q++) c[i][j][q] = 0.f;

    int iters = kPerZ >> 5;
    // prologue: stage 0
    CP_ASYNC16(s2u(&sA[0][r0][c0]), pA0 + k0);
    CP_ASYNC16(s2u(&sA[0][r1][c1]), pA1 + k0);
    CP_ASYNC16(s2u(&sB[0][r0][c0]), pB0 + k0);
    CP_ASYNC16(s2u(&sB[0][r1][c1]), pB1 + k0);
    CP_COMMIT();

    for (int it = 0; it < iters; ++it) {
        if (it + 1 < iters) {
            int s = (it + 1) & 1;
            int kb = k0 + (it + 1) * 32;
            CP_ASYNC16(s2u(&sA[s][r0][c0]), pA0 + kb);
            CP_ASYNC16(s2u(&sA[s][r1][c1]), pA1 + kb);
            CP_ASYNC16(s2u(&sB[s][r0][c0]), pB0 + kb);
            CP_ASYNC16(s2u(&sB[s][r1][c1]), pB1 + kb);
            CP_COMMIT();
            CP_WAIT(1);
        } else {
            CP_WAIT(0);
        }
        __syncthreads();
        int cs = it & 1;
#pragma unroll
        for (int ks = 0; ks < 2; ks++) {
            int kk = ks * 16;
            uint32_t a[4][4], b[4][2];
#pragma unroll
            for (int mi = 0; mi < 4; mi++) {
                uint32_t addr = s2u(&sA[cs][wm + mi * 16 + (lane & 15)][kk + (lane >> 4) * 8]);
                asm volatile("ldmatrix.sync.aligned.m8n8.x4.shared.b16 {%0,%1,%2,%3}, [%4];"
                             : "=r"(a[mi][0]), "=r"(a[mi][1]), "=r"(a[mi][2]), "=r"(a[mi][3])
                             : "r"(addr));
            }
#pragma unroll
            for (int ni = 0; ni < 4; ni++) {
                int l = lane & 15;
                uint32_t addr = s2u(&sB[cs][wn + ni * 8 + (l & 7)][kk + (l >> 3) * 8]);
                asm volatile("ldmatrix.sync.aligned.m8n8.x2.shared.b16 {%0,%1}, [%2];"
                             : "=r"(b[ni][0]), "=r"(b[ni][1]) : "r"(addr));
            }
#pragma unroll
            for (int mi = 0; mi < 4; mi++)
#pragma unroll
                for (int ni = 0; ni < 4; ni++)
                    asm volatile(
                        "mma.sync.aligned.m16n8k16.row.col.f32.bf16.bf16.f32 "
                        "{%0,%1,%2,%3}, {%4,%5,%6,%7}, {%8,%9}, {%0,%1,%2,%3};"
                        : "+f"(c[mi][ni][0]), "+f"(c[mi][ni][1]),
                          "+f"(c[mi][ni][2]), "+f"(c[mi][ni][3])
                        : "r"(a[mi][0]), "r"(a[mi][1]), "r"(a[mi][2]), "r"(a[mi][3]),
                          "r"(b[ni][0]), "r"(b[ni][1]));
        }
        __syncthreads();
    }

    // ---------------- epilogues ----------------
    if (EPI == 0) {
        float g = sigmoidf_(gate[0]);
#pragma unroll
        for (int mi = 0; mi < 4; mi++) {
            int row0 = bm + wm + mi * 16 + (lane >> 2);
#pragma unroll
            for (int rr = 0; rr < 2; rr++) {
                int row = row0 + rr * 8;           // window index
                if (row >= BW) continue;
                int b   = row / (NWH * NWH);
                int r2  = row % (NWH * NWH);
                int wh  = r2 / NWH, ww = r2 % NWH;
#pragma unroll
                for (int ni = 0; ni < 4; ni++) {
                    int col = bn + wn + ni * 8 + (lane & 3) * 2;
                    int wpos = col / C_;
                    int ch   = col - wpos * C_;
                    int hr = wh * 4 + (wpos >> 2);
                    int wr = ww * 4 + (wpos & 3);
                    int h = hr + 2; if (h >= H_) h -= H_;
                    int w = wr + 2; if (w >= W_) w -= W_;
                    size_t pix = ((size_t)(b * H_ + h) * W_ + w) * C_ + ch;
                    float v0 = c[mi][ni][rr * 2 + 0];
                    float v1 = c[mi][ni][rr * 2 + 1];
                    float m0 = sigmoidf_(v0 + bias[col]);
                    float m1 = sigmoidf_(v1 + bias[col + 1]);
                    float2 xv = *(const float2*)(xres + pix);
                    float2 o;
                    o.x = xv.x + g * m0 + (1.0f - g) * sigmoidf_(m0);
                    o.y = xv.y + g * m1 + (1.0f - g) * sigmoidf_(m1);
                    *(float2*)(out + pix) = o;
                }
            }
        }
    } else {
#pragma unroll
        for (int mi = 0; mi < 4; mi++) {
            int row = bm + wm + mi * 16 + (lane >> 2);
#pragma unroll
            for (int ni = 0; ni < 4; ni++) {
                int col = bn + wn + ni * 8 + (lane & 3) * 2;
                float v0 = c[mi][ni][0], v1 = c[mi][ni][1];
                float v2 = c[mi][ni][2], v3 = c[mi][ni][3];
                if (EPI == 1) {
                    if (col < nValid) {
                        *(__nv_bfloat162*)(Cb + (size_t)row * ldc + col) =
                            __floats2bfloat162_rn(v0 * scale, v1 * scale);
                        *(__nv_bfloat162*)(Cb + (size_t)(row + 8) * ldc + col) =
                            __floats2bfloat162_rn(v2 * scale, v3 * scale);
                    }
                } else {
                    *(float2*)(Cf + (size_t)row * ldc + col) = make_float2(v0, v1);
                    *(float2*)(Cf + (size_t)(row + 8) * ldc + col) = make_float2(v2, v3);
                }
            }
        }
    }
}

// ---------------- fused: combine split-K -> literal bits -> clauses ----------
__global__ void combine_clause_kernel(const float* __restrict__ b1,
                                      float* __restrict__ out_cl,
                                      float* __restrict__ out_sum) {
    __shared__ uint32_t slit[16];
    __shared__ uint32_t scnt[8];
    int row = blockIdx.x;       // 0..MP-1
    int c   = threadIdx.x;      // 0..255  (feature, then clause)
    float s = b1[c];
#pragma unroll
    for (int z = 0; z < KSPL; z++) s += g_part[(size_t)z * MP * HID + (size_t)row * HID + c];
    uint32_t mp = __ballot_sync(0xffffffffu, s > 0.0f);
    uint32_t mn = __ballot_sync(0xffffffffu, s < 0.0f);
    if ((c & 31) == 0) {
        slit[c >> 5]       = mp;
        slit[8 + (c >> 5)] = mn;
    }
    __syncthreads();
    uint32_t viol = 0;
#pragma unroll
    for (int i = 0; i < 16; i++) viol |= g_incb[i * NCL + c] & ~slit[i];
    float cv = (viol == 0u) ? 1.0f : 0.0f;
    g_clb[(size_t)row * NCL + c] = __float2bfloat16_rn(cv);
    if (row < BW) out_cl[(size_t)row * NCL + c] = cv;
    // summary = popcount of clause bits / 256
    uint32_t cm = __ballot_sync(0xffffffffu, viol == 0u);
    if ((c & 31) == 0) scnt[c >> 5] = (uint32_t)__popc(cm);
    __syncthreads();
    if (c == 0 && row < BW) {
        uint32_t tot = 0;
#pragma unroll
        for (int i = 0; i < 8; i++) tot += scnt[i];
        out_sum[row] = (float)tot * (1.0f / NCL);
    }
}

// ---------------- host launcher -----------------------------------------------
static void* sym_addr(const void* sym) {
    void* p = nullptr;
    cudaGetSymbolAddress(&p, sym);
    return p;
}

extern "C" void kernel_launch(void* const* d_in, const int* in_sizes, int n_in,
                              void* d_out, int out_size) {
    const float* x      = (const float*)d_in[0];
    const float* gamma  = (const float*)d_in[1];
    const float* beta   = (const float*)d_in[2];
    const float* W1     = (const float*)d_in[3];
    const float* b1     = (const float*)d_in[4];
    const float* inc_w  = (const float*)d_in[5];
    const float* vote_w = (const float*)d_in[6];
    const float* W2     = (const float*)d_in[7];
    const float* b2     = (const float*)d_in[8];
    const float* gate   = (const float*)d_in[9];

    float* out     = (float*)d_out;
    float* out_cl  = out + (size_t)B_ * H_ * W_ * C_;
    float* out_sum = out_cl + (size_t)BW * NCL;

    __nv_bfloat16* p_win  = (__nv_bfloat16*)sym_addr(g_win);
    __nv_bfloat16* p_W1T  = (__nv_bfloat16*)sym_addr(g_W1T);
    __nv_bfloat16* p_W2T  = (__nv_bfloat16*)sym_addr(g_W2T);
    __nv_bfloat16* p_vwT  = (__nv_bfloat16*)sym_addr(g_vwT);
    __nv_bfloat16* p_clb  = (__nv_bfloat16*)sym_addr(g_clb);
    __nv_bfloat16* p_logb = (__nv_bfloat16*)sym_addr(g_logb);
    float*         p_part = (float*)sym_addr(g_part);

    // 1) LN + roll + window partition -> bf16
    ln_partition_kernel<<<3136, 256>>>(x, gamma, beta);
    // 2) fused prep: weight transposes + include bitpack
    prep_fused_kernel<<<SEGT / 256, 256>>>(W1, W2, vote_w, inc_w);
    // 3) GEMM1 (split-K=4): partials = win @ W1
    mma_gemm<2><<<dim3(2, 13, KSPL), 256>>>(p_win, IND, p_W1T, IND, nullptr, 0.f,
                                            p_part, nullptr, HID, HID, IND / KSPL, MP * HID,
                                            nullptr, nullptr, nullptr);
    // 4) combine partials -> literal bits -> clause bits + outputs
    combine_clause_kernel<<<MP, 256>>>(b1, out_cl, out_sum);
    // 5) GEMM2: logits = clauses @ vote_w / 16 -> bf16
    mma_gemm<1><<<dim3(2, 13, 1), 256>>>(p_clb, NCL, p_vwT, NCL, nullptr, 0.0625f,
                                         nullptr, p_logb, C_, C_, NCL, 0,
                                         nullptr, nullptr, nullptr);
    // 6) GEMM3 + fused final: out = x + blend(sigmoid(logits @ W2 + b2))
    mma_gemm<0><<<dim3(24, 13, 1), 256>>>(p_logb, C_, p_W2T, C_, b2, 0.f,
                                          nullptr, nullptr, IND, IND, C_, 0,
                                          x, gate, out);
}